// round 8
// baseline (speedup 1.0000x reference)
#include <cuda_runtime.h>
#include <cuda_bf16.h>
#include <math.h>
#include <stdint.h>

#define N_ROWS 8192
#define DIM    1024
#define BM     128          // CTA rows (ex)
#define BN     128          // CTA cols (ey)
#define BKB    128          // k bytes (int8 elems) per pipeline chunk
#define NCHUNK (DIM / BKB)  // 8
#define NSTAGE 3
#define SSTRIDE_B 144       // padded bytes per smem row -> conflict-free ldmatrix
#define A_STAGE_BYTES (BM * SSTRIDE_B)                // 18432
#define B_STAGE_BYTES (BN * SSTRIDE_B)                // 18432
#define STAGE_BYTES   (A_STAGE_BYTES + B_STAGE_BYTES) // 36864
#define SMEM_PIPE     (NSTAGE * STAGE_BYTES)          // 110592
#define RMAX_OFF      SMEM_PIPE                       // 128 ints
#define CMAX_OFF      (SMEM_PIPE + 512)               // 128 ints
#define SMEM_DYN      (SMEM_PIPE + 1024)              // 111616 -> 2 CTAs/SM

#define QSCALE 512.0f       // int8 quantization scale; dots carry 512^2 x
#define INT_NEG_INF (-2147483647 - 1)

// Scratch (no cudaMalloc allowed): int8 normalized copies + int max accumulators.
__device__ unsigned char g_exn8[(size_t)N_ROWS * DIM];
__device__ unsigned char g_eyn8[(size_t)N_ROWS * DIM];
__device__ int g_rowmax[N_ROWS];
__device__ int g_colmax[N_ROWS];

__device__ __forceinline__ void cp_async16(uint32_t s, const void* g) {
    asm volatile("cp.async.cg.shared.global [%0], [%1], 16;" :: "r"(s), "l"(g));
}
__device__ __forceinline__ void cp_commit() {
    asm volatile("cp.async.commit_group;" ::: "memory");
}
template <int N>
__device__ __forceinline__ void cp_wait() {
    asm volatile("cp.async.wait_group %0;" :: "n"(N) : "memory");
}

// ---------------------------------------------------------------------------
// Kernel 0: reset max accumulators
// ---------------------------------------------------------------------------
__global__ void init_kernel() {
    int i = blockIdx.x * blockDim.x + threadIdx.x;
    if (i < N_ROWS) g_rowmax[i] = INT_NEG_INF;
    else            g_colmax[i - N_ROWS] = INT_NEG_INF;
}

// ---------------------------------------------------------------------------
// Kernel 1: fp32 row L2-normalize, quantize to int8 (round, clamp +-127).
// ---------------------------------------------------------------------------
__global__ void __launch_bounds__(256) normalize_kernel(const float* __restrict__ ex,
                                                        const float* __restrict__ ey) {
    __shared__ float sh[8];
    int row = blockIdx.x;
    const float* src;
    unsigned char* dst;
    if (row < N_ROWS) {
        src = ex + (size_t)row * DIM;
        dst = g_exn8 + (size_t)row * DIM;
    } else {
        src = ey + (size_t)(row - N_ROWS) * DIM;
        dst = g_eyn8 + (size_t)(row - N_ROWS) * DIM;
    }
    int tid = threadIdx.x;
    float4 v = reinterpret_cast<const float4*>(src)[tid];
    float ss = v.x * v.x + v.y * v.y + v.z * v.z + v.w * v.w;
    #pragma unroll
    for (int o = 16; o; o >>= 1) ss += __shfl_xor_sync(0xffffffffu, ss, o);
    if ((tid & 31) == 0) sh[tid >> 5] = ss;
    __syncthreads();
    float tot = 0.f;
    #pragma unroll
    for (int w = 0; w < 8; w++) tot += sh[w];
    float inv = rsqrtf(tot) * QSCALE;
    int q0 = max(-127, min(127, __float2int_rn(v.x * inv)));
    int q1 = max(-127, min(127, __float2int_rn(v.y * inv)));
    int q2 = max(-127, min(127, __float2int_rn(v.z * inv)));
    int q3 = max(-127, min(127, __float2int_rn(v.w * inv)));
    uint32_t packed = (uint32_t)(q0 & 0xFF) | ((uint32_t)(q1 & 0xFF) << 8) |
                      ((uint32_t)(q2 & 0xFF) << 16) | ((uint32_t)(q3 & 0xFF) << 24);
    reinterpret_cast<uint32_t*>(dst)[tid] = packed;
}

// ---------------------------------------------------------------------------
// Kernel 2: pipelined int8 IMMA GEMM (128x128 CTA tile), fused int max-reduce.
// 8 warps: 4 warp-rows x 2 warp-cols; warp tile 32x64. 2 CTAs/SM.
// ---------------------------------------------------------------------------
__device__ __forceinline__ void load_chunk(uint32_t sbase, int s, int kc,
                                           int rowBase, int colBase, int tid) {
    uint32_t stA = sbase + s * STAGE_BYTES;
    uint32_t stB = stA + A_STAGE_BYTES;
    const unsigned char* gA = g_exn8 + (size_t)rowBase * DIM + kc * BKB;
    const unsigned char* gB = g_eyn8 + (size_t)colBase * DIM + kc * BKB;
    #pragma unroll
    for (int t = 0; t < 4; t++) {           // A: 128 rows x 128 bytes
        int idx = tid + t * 256;            // 0..1023
        int r = idx >> 3;                   // 0..127
        int c = idx & 7;                    // 16B unit
        cp_async16(stA + r * SSTRIDE_B + c * 16, gA + (size_t)r * DIM + c * 16);
    }
    #pragma unroll
    for (int t = 0; t < 4; t++) {           // B: 128 rows x 128 bytes
        int idx = tid + t * 256;
        int r = idx >> 3;
        int c = idx & 7;
        cp_async16(stB + r * SSTRIDE_B + c * 16, gB + (size_t)r * DIM + c * 16);
    }
}

__global__ void __launch_bounds__(256, 2) gemm_max_kernel() {
    extern __shared__ char dsm[];
    const int tid  = threadIdx.x;
    const int lane = tid & 31;
    const int wid  = tid >> 5;
    const int warpRow = wid & 3;      // 0..3 -> 32-row slab
    const int warpCol = wid >> 2;     // 0..1 -> 64-col slab
    const int rowBase = blockIdx.y * BM;
    const int colBase = blockIdx.x * BN;

    uint32_t sbase = (uint32_t)__cvta_generic_to_shared(dsm);
    int* s_rmax = reinterpret_cast<int*>(dsm + RMAX_OFF);
    int* s_cmax = reinterpret_cast<int*>(dsm + CMAX_OFF);
    if (tid < BM) s_rmax[tid] = INT_NEG_INF;
    if (tid < BN) s_cmax[tid] = INT_NEG_INF;

    int acc[2][8][4];
    #pragma unroll
    for (int i = 0; i < 2; i++)
        #pragma unroll
        for (int j = 0; j < 8; j++)
            #pragma unroll
            for (int r = 0; r < 4; r++) acc[i][j][r] = 0;

    load_chunk(sbase, 0, 0, rowBase, colBase, tid); cp_commit();
    load_chunk(sbase, 1, 1, rowBase, colBase, tid); cp_commit();

    for (int ch = 0; ch < NCHUNK; ch++) {
        int s = ch % NSTAGE;
        if (ch < NCHUNK - 1) cp_wait<1>(); else cp_wait<0>();
        __syncthreads();

        if (ch + 2 < NCHUNK) {
            load_chunk(sbase, (ch + 2) % NSTAGE, ch + 2, rowBase, colBase, tid);
            cp_commit();
        }

        uint32_t stA = sbase + s * STAGE_BYTES;
        uint32_t stB = stA + A_STAGE_BYTES;

        #pragma unroll
        for (int kk = 0; kk < 4; kk++) {     // 4 x k32 steps per 128B chunk
            uint32_t a[2][4];
            uint32_t b[8][2];
            // A fragments: m16 x k32 per x4 ldmatrix (byte layout = fp8 k32).
            #pragma unroll
            for (int i = 0; i < 2; i++) {
                int r  = warpRow * 32 + i * 16 + ((lane >> 3) & 1) * 8 + (lane & 7);
                int kb = kk * 32 + (lane >> 4) * 16;
                uint32_t addr = stA + r * SSTRIDE_B + kb;
                asm volatile("ldmatrix.sync.aligned.m8n8.x4.shared.b16 {%0,%1,%2,%3}, [%4];"
                             : "=r"(a[i][0]), "=r"(a[i][1]), "=r"(a[i][2]), "=r"(a[i][3])
                             : "r"(addr));
            }
            // B fragments: two n8 k32 tiles per x4 ldmatrix.
            #pragma unroll
            for (int j = 0; j < 4; j++) {
                int n  = warpCol * 64 + j * 16 + (lane >> 4) * 8 + (lane & 7);
                int kb = kk * 32 + ((lane >> 3) & 1) * 16;
                uint32_t addr = stB + n * SSTRIDE_B + kb;
                asm volatile("ldmatrix.sync.aligned.m8n8.x4.shared.b16 {%0,%1,%2,%3}, [%4];"
                             : "=r"(b[2 * j][0]), "=r"(b[2 * j][1]),
                               "=r"(b[2 * j + 1][0]), "=r"(b[2 * j + 1][1])
                             : "r"(addr));
            }
            #pragma unroll
            for (int i = 0; i < 2; i++)
                #pragma unroll
                for (int j = 0; j < 8; j++)
                    asm volatile(
                        "mma.sync.aligned.m16n8k32.row.col.s32.s8.s8.s32 "
                        "{%0,%1,%2,%3}, {%4,%5,%6,%7}, {%8,%9}, {%0,%1,%2,%3};"
                        : "+r"(acc[i][j][0]), "+r"(acc[i][j][1]),
                          "+r"(acc[i][j][2]), "+r"(acc[i][j][3])
                        : "r"(a[i][0]), "r"(a[i][1]), "r"(a[i][2]), "r"(a[i][3]),
                          "r"(b[j][0]), "r"(b[j][1]));
        }
        __syncthreads();
    }

    // ---- Row maxes (acc carries 512^2 x cosine; rescaled in finalize) ----
    #pragma unroll
    for (int i = 0; i < 2; i++) {
        #pragma unroll
        for (int half = 0; half < 2; half++) {
            int m = INT_NEG_INF;
            #pragma unroll
            for (int j = 0; j < 8; j++)
                m = max(m, max(acc[i][j][half * 2], acc[i][j][half * 2 + 1]));
            m = max(m, __shfl_xor_sync(0xffffffffu, m, 1));
            m = max(m, __shfl_xor_sync(0xffffffffu, m, 2));
            if ((lane & 3) == 0)
                atomicMax(&s_rmax[warpRow * 32 + i * 16 + half * 8 + (lane >> 2)], m);
        }
    }
    // ---- Col maxes ----
    #pragma unroll
    for (int j = 0; j < 8; j++) {
        #pragma unroll
        for (int q = 0; q < 2; q++) {
            int m = INT_NEG_INF;
            #pragma unroll
            for (int i = 0; i < 2; i++)
                m = max(m, max(acc[i][j][q], acc[i][j][q + 2]));
            m = max(m, __shfl_xor_sync(0xffffffffu, m, 4));
            m = max(m, __shfl_xor_sync(0xffffffffu, m, 8));
            m = max(m, __shfl_xor_sync(0xffffffffu, m, 16));
            if (lane < 4)
                atomicMax(&s_cmax[warpCol * 64 + j * 8 + (lane & 3) * 2 + q], m);
        }
    }
    __syncthreads();
    if (tid < BM) atomicMax(&g_rowmax[rowBase + tid], s_rmax[tid]);
    if (tid < BN) atomicMax(&g_colmax[colBase + tid], s_cmax[tid]);
}

// ---------------------------------------------------------------------------
// Kernel 3: sum max vectors (undo 512^2 scale), entropy transform, out[2].
// ---------------------------------------------------------------------------
__global__ void __launch_bounds__(256) finalize_kernel(float* __restrict__ out) {
    __shared__ float sh[16];
    int tid = threadIdx.x;
    float sr = 0.f, sc = 0.f;
    for (int i = tid; i < N_ROWS; i += 256) {
        sr += (float)g_rowmax[i];
        sc += (float)g_colmax[i];
    }
    #pragma unroll
    for (int o = 16; o; o >>= 1) {
        sr += __shfl_xor_sync(0xffffffffu, sr, o);
        sc += __shfl_xor_sync(0xffffffffu, sc, o);
    }
    if ((tid & 31) == 0) {
        sh[tid >> 5]       = sr;
        sh[8 + (tid >> 5)] = sc;
    }
    __syncthreads();
    if (tid == 0) {
        float SR = 0.f, SC = 0.f;
        #pragma unroll
        for (int w = 0; w < 8; w++) { SR += sh[w]; SC += sh[8 + w]; }
        const float invs2 = 1.0f / (QSCALE * QSCALE);
        const double sigma = 0.3;
        float hc = (float)(0.5 * log(6.283185307179586 * sigma * sigma) + 0.5);
        out[0] = hc * ((float)N_ROWS - SR * invs2) / 0.3f;
        out[1] = hc * ((float)N_ROWS - SC * invs2) / 0.3f;
    }
}

// ---------------------------------------------------------------------------
extern "C" void kernel_launch(void* const* d_in, const int* in_sizes, int n_in,
                              void* d_out, int out_size) {
    const float* ex = (const float*)d_in[0];
    const float* ey = (const float*)d_in[1];
    float* out = (float*)d_out;

    cudaFuncSetAttribute(gemm_max_kernel,
                         cudaFuncAttributeMaxDynamicSharedMemorySize, SMEM_DYN);

    init_kernel<<<(2 * N_ROWS) / 256, 256>>>();
    normalize_kernel<<<2 * N_ROWS, 256>>>(ex, ey);
    dim3 grid(N_ROWS / BN, N_ROWS / BM);
    gemm_max_kernel<<<grid, 256, SMEM_DYN>>>();
    finalize_kernel<<<1, 256>>>(out);
}

// round 9
// speedup vs baseline: 2.4988x; 2.4988x over previous
#include <cuda_runtime.h>
#include <cuda_bf16.h>
#include <cuda_fp16.h>
#include <cuda_fp8.h>
#include <math.h>
#include <stdint.h>

#define N_ROWS 8192
#define DIM    1024
#define BM     128          // CTA rows (ex)
#define BN     128          // CTA cols (ey)
#define BKB    128          // k bytes (fp8 elems) per pipeline chunk
#define NCHUNK (DIM / BKB)  // 8
#define NSTAGE 3
#define SSTRIDE_B 144       // padded bytes per smem row -> conflict-free ldmatrix
#define A_STAGE_BYTES (BM * SSTRIDE_B)                // 18432
#define B_STAGE_BYTES (BN * SSTRIDE_B)                // 18432
#define STAGE_BYTES   (A_STAGE_BYTES + B_STAGE_BYTES) // 36864
#define SMEM_PIPE     (NSTAGE * STAGE_BYTES)          // 110592
#define RMAX_OFF      SMEM_PIPE                       // 128 floats
#define CMAX_OFF      (SMEM_PIPE + 512)               // 128 floats
#define SMEM_DYN      (SMEM_PIPE + 1024)              // 111616 -> 2 CTAs/SM

#define SCALE 16.0f         // pre-quantization scale; dots carry 256x

// Scratch (no cudaMalloc allowed): fp8 normalized copies + max accumulators.
__device__ unsigned char g_exn8[(size_t)N_ROWS * DIM];
__device__ unsigned char g_eyn8[(size_t)N_ROWS * DIM];
__device__ float g_rowmax[N_ROWS];
__device__ float g_colmax[N_ROWS];

__device__ __forceinline__ void atomicMaxF(float* addr, float val) {
    if (__float_as_int(val) >= 0) {
        atomicMax(reinterpret_cast<int*>(addr), __float_as_int(val));
    } else {
        atomicMin(reinterpret_cast<unsigned int*>(addr), __float_as_uint(val));
    }
}

__device__ __forceinline__ void cp_async16(uint32_t s, const void* g) {
    asm volatile("cp.async.cg.shared.global [%0], [%1], 16;" :: "r"(s), "l"(g));
}
__device__ __forceinline__ void cp_commit() {
    asm volatile("cp.async.commit_group;" ::: "memory");
}
template <int N>
__device__ __forceinline__ void cp_wait() {
    asm volatile("cp.async.wait_group %0;" :: "n"(N) : "memory");
}

// ---------------------------------------------------------------------------
// Kernel 0: reset max accumulators
// ---------------------------------------------------------------------------
__global__ void init_kernel() {
    int i = blockIdx.x * blockDim.x + threadIdx.x;
    if (i < N_ROWS) g_rowmax[i] = -INFINITY;
    else            g_colmax[i - N_ROWS] = -INFINITY;
}

// ---------------------------------------------------------------------------
// Kernel 1: fp32 row L2-normalize, scale by 16, emit fp8 e4m3.
// ---------------------------------------------------------------------------
__global__ void __launch_bounds__(256) normalize_kernel(const float* __restrict__ ex,
                                                        const float* __restrict__ ey) {
    __shared__ float sh[8];
    int row = blockIdx.x;
    const float* src;
    unsigned char* dst;
    if (row < N_ROWS) {
        src = ex + (size_t)row * DIM;
        dst = g_exn8 + (size_t)row * DIM;
    } else {
        src = ey + (size_t)(row - N_ROWS) * DIM;
        dst = g_eyn8 + (size_t)(row - N_ROWS) * DIM;
    }
    int tid = threadIdx.x;
    float4 v = reinterpret_cast<const float4*>(src)[tid];
    float ss = v.x * v.x + v.y * v.y + v.z * v.z + v.w * v.w;
    #pragma unroll
    for (int o = 16; o; o >>= 1) ss += __shfl_xor_sync(0xffffffffu, ss, o);
    if ((tid & 31) == 0) sh[tid >> 5] = ss;
    __syncthreads();
    float tot = 0.f;
    #pragma unroll
    for (int w = 0; w < 8; w++) tot += sh[w];
    float inv = rsqrtf(tot) * SCALE;
    uint32_t b0 = __nv_cvt_float_to_fp8(v.x * inv, __NV_SATFINITE, __NV_E4M3);
    uint32_t b1 = __nv_cvt_float_to_fp8(v.y * inv, __NV_SATFINITE, __NV_E4M3);
    uint32_t b2 = __nv_cvt_float_to_fp8(v.z * inv, __NV_SATFINITE, __NV_E4M3);
    uint32_t b3 = __nv_cvt_float_to_fp8(v.w * inv, __NV_SATFINITE, __NV_E4M3);
    reinterpret_cast<uint32_t*>(dst)[tid] = b0 | (b1 << 8) | (b2 << 16) | (b3 << 24);
}

// ---------------------------------------------------------------------------
// Kernel 2: pipelined fp8 mma.sync GEMM with f16 accumulators (128x128 CTA),
// fused max-reduce. 8 warps: 4 warp-rows x 2 warp-cols; warp tile 32x64.
// 2 CTAs/SM (111.6KB smem).
// ---------------------------------------------------------------------------
__device__ __forceinline__ void load_chunk(uint32_t sbase, int s, int kc,
                                           int rowBase, int colBase, int tid) {
    uint32_t stA = sbase + s * STAGE_BYTES;
    uint32_t stB = stA + A_STAGE_BYTES;
    const unsigned char* gA = g_exn8 + (size_t)rowBase * DIM + kc * BKB;
    const unsigned char* gB = g_eyn8 + (size_t)colBase * DIM + kc * BKB;
    #pragma unroll
    for (int t = 0; t < 4; t++) {           // A: 128 rows x 128 bytes
        int idx = tid + t * 256;            // 0..1023
        int r = idx >> 3;                   // 0..127
        int c = idx & 7;                    // 16B unit
        cp_async16(stA + r * SSTRIDE_B + c * 16, gA + (size_t)r * DIM + c * 16);
    }
    #pragma unroll
    for (int t = 0; t < 4; t++) {           // B: 128 rows x 128 bytes
        int idx = tid + t * 256;
        int r = idx >> 3;
        int c = idx & 7;
        cp_async16(stB + r * SSTRIDE_B + c * 16, gB + (size_t)r * DIM + c * 16);
    }
}

__global__ void __launch_bounds__(256, 2) gemm_max_kernel() {
    extern __shared__ char dsm[];
    const int tid  = threadIdx.x;
    const int lane = tid & 31;
    const int wid  = tid >> 5;
    const int warpRow = wid & 3;      // 0..3 -> 32-row slab
    const int warpCol = wid >> 2;     // 0..1 -> 64-col slab
    const int rowBase = blockIdx.y * BM;
    const int colBase = blockIdx.x * BN;

    uint32_t sbase = (uint32_t)__cvta_generic_to_shared(dsm);
    float* s_rmax = reinterpret_cast<float*>(dsm + RMAX_OFF);
    float* s_cmax = reinterpret_cast<float*>(dsm + CMAX_OFF);
    if (tid < BM) s_rmax[tid] = -INFINITY;
    if (tid < BN) s_cmax[tid] = -INFINITY;

    // f16 accumulators: [mtile][ntile][rowhalf], each u32 = 2 packed f16 cols
    uint32_t acc[2][8][2];
    #pragma unroll
    for (int i = 0; i < 2; i++)
        #pragma unroll
        for (int j = 0; j < 8; j++) {
            acc[i][j][0] = 0u;
            acc[i][j][1] = 0u;
        }

    load_chunk(sbase, 0, 0, rowBase, colBase, tid); cp_commit();
    load_chunk(sbase, 1, 1, rowBase, colBase, tid); cp_commit();

    for (int ch = 0; ch < NCHUNK; ch++) {
        int s = ch % NSTAGE;
        if (ch < NCHUNK - 1) cp_wait<1>(); else cp_wait<0>();
        __syncthreads();

        if (ch + 2 < NCHUNK) {
            load_chunk(sbase, (ch + 2) % NSTAGE, ch + 2, rowBase, colBase, tid);
            cp_commit();
        }

        uint32_t stA = sbase + s * STAGE_BYTES;
        uint32_t stB = stA + A_STAGE_BYTES;

        #pragma unroll
        for (int kk = 0; kk < 4; kk++) {     // 4 x k32 steps per 128B chunk
            uint32_t a[2][4];
            uint32_t b[8][2];
            #pragma unroll
            for (int i = 0; i < 2; i++) {
                int r  = warpRow * 32 + i * 16 + ((lane >> 3) & 1) * 8 + (lane & 7);
                int kb = kk * 32 + (lane >> 4) * 16;
                uint32_t addr = stA + r * SSTRIDE_B + kb;
                asm volatile("ldmatrix.sync.aligned.m8n8.x4.shared.b16 {%0,%1,%2,%3}, [%4];"
                             : "=r"(a[i][0]), "=r"(a[i][1]), "=r"(a[i][2]), "=r"(a[i][3])
                             : "r"(addr));
            }
            #pragma unroll
            for (int j = 0; j < 4; j++) {
                int n  = warpCol * 64 + j * 16 + (lane >> 4) * 8 + (lane & 7);
                int kb = kk * 32 + ((lane >> 3) & 1) * 16;
                uint32_t addr = stB + n * SSTRIDE_B + kb;
                asm volatile("ldmatrix.sync.aligned.m8n8.x4.shared.b16 {%0,%1,%2,%3}, [%4];"
                             : "=r"(b[2 * j][0]), "=r"(b[2 * j][1]),
                               "=r"(b[2 * j + 1][0]), "=r"(b[2 * j + 1][1])
                             : "r"(addr));
            }
            #pragma unroll
            for (int i = 0; i < 2; i++)
                #pragma unroll
                for (int j = 0; j < 8; j++)
                    asm volatile(
                        "mma.sync.aligned.m16n8k32.row.col.f16.e4m3.e4m3.f16 "
                        "{%0,%1}, {%2,%3,%4,%5}, {%6,%7}, {%0,%1};"
                        : "+r"(acc[i][j][0]), "+r"(acc[i][j][1])
                        : "r"(a[i][0]), "r"(a[i][1]), "r"(a[i][2]), "r"(a[i][3]),
                          "r"(b[j][0]), "r"(b[j][1]));
        }
        __syncthreads();
    }

    // ---- Row maxes: reg h covers row groupID+8h, packed pair = 2 adjacent cols.
    #pragma unroll
    for (int i = 0; i < 2; i++) {
        #pragma unroll
        for (int h = 0; h < 2; h++) {
            __half2 hm = *reinterpret_cast<__half2*>(&acc[i][0][h]);
            #pragma unroll
            for (int j = 1; j < 8; j++)
                hm = __hmax2(hm, *reinterpret_cast<__half2*>(&acc[i][j][h]));
            float m = fmaxf(__low2float(hm), __high2float(hm));
            m = fmaxf(m, __shfl_xor_sync(0xffffffffu, m, 1));
            m = fmaxf(m, __shfl_xor_sync(0xffffffffu, m, 2));
            if ((lane & 3) == 0)
                atomicMaxF(&s_rmax[warpRow * 32 + i * 16 + h * 8 + (lane >> 2)], m);
        }
    }
    // ---- Col maxes: packed lanes are 2 adjacent cols -> reduce as half2.
    #pragma unroll
    for (int j = 0; j < 8; j++) {
        __half2 mm = __hmax2(
            __hmax2(*reinterpret_cast<__half2*>(&acc[0][j][0]),
                    *reinterpret_cast<__half2*>(&acc[0][j][1])),
            __hmax2(*reinterpret_cast<__half2*>(&acc[1][j][0]),
                    *reinterpret_cast<__half2*>(&acc[1][j][1])));
        #pragma unroll
        for (int o = 4; o <= 16; o <<= 1) {
            uint32_t u = __shfl_xor_sync(0xffffffffu,
                                         *reinterpret_cast<uint32_t*>(&mm), o);
            mm = __hmax2(mm, *reinterpret_cast<__half2*>(&u));
        }
        if (lane < 4) {
            int cbase = warpCol * 64 + j * 8 + (lane & 3) * 2;
            atomicMaxF(&s_cmax[cbase],     __low2float(mm));
            atomicMaxF(&s_cmax[cbase + 1], __high2float(mm));
        }
    }
    __syncthreads();
    if (tid < BM) atomicMaxF(&g_rowmax[rowBase + tid], s_rmax[tid]);
    if (tid < BN) atomicMaxF(&g_colmax[colBase + tid], s_cmax[tid]);
}

// ---------------------------------------------------------------------------
// Kernel 3: sum max vectors (undo 256x scale), entropy transform, out[2].
// ---------------------------------------------------------------------------
__global__ void __launch_bounds__(256) finalize_kernel(float* __restrict__ out) {
    __shared__ float sh[16];
    int tid = threadIdx.x;
    float sr = 0.f, sc = 0.f;
    for (int i = tid; i < N_ROWS; i += 256) {
        sr += g_rowmax[i];
        sc += g_colmax[i];
    }
    #pragma unroll
    for (int o = 16; o; o >>= 1) {
        sr += __shfl_xor_sync(0xffffffffu, sr, o);
        sc += __shfl_xor_sync(0xffffffffu, sc, o);
    }
    if ((tid & 31) == 0) {
        sh[tid >> 5]       = sr;
        sh[8 + (tid >> 5)] = sc;
    }
    __syncthreads();
    if (tid == 0) {
        float SR = 0.f, SC = 0.f;
        #pragma unroll
        for (int w = 0; w < 8; w++) { SR += sh[w]; SC += sh[8 + w]; }
        const float invs2 = 1.0f / (SCALE * SCALE);
        const double sigma = 0.3;
        float hc = (float)(0.5 * log(6.283185307179586 * sigma * sigma) + 0.5);
        out[0] = hc * ((float)N_ROWS - SR * invs2) / 0.3f;
        out[1] = hc * ((float)N_ROWS - SC * invs2) / 0.3f;
    }
}

// ---------------------------------------------------------------------------
extern "C" void kernel_launch(void* const* d_in, const int* in_sizes, int n_in,
                              void* d_out, int out_size) {
    const float* ex = (const float*)d_in[0];
    const float* ey = (const float*)d_in[1];
    float* out = (float*)d_out;

    cudaFuncSetAttribute(gemm_max_kernel,
                         cudaFuncAttributeMaxDynamicSharedMemorySize, SMEM_DYN);

    init_kernel<<<(2 * N_ROWS) / 256, 256>>>();
    normalize_kernel<<<2 * N_ROWS, 256>>>(ex, ey);
    dim3 grid(N_ROWS / BN, N_ROWS / BM);
    gemm_max_kernel<<<grid, 256, SMEM_DYN>>>();
    finalize_kernel<<<1, 256>>>(out);
}

// round 11
// speedup vs baseline: 2.6673x; 1.0675x over previous
#include <cuda_runtime.h>
#include <cuda_bf16.h>
#include <cuda_fp16.h>
#include <cuda_fp8.h>
#include <math.h>
#include <stdint.h>

#define N_ROWS 8192
#define DIM    1024
#define BM     128          // CTA rows (ex)
#define BN     128          // CTA cols (ey)
#define BKB    128          // k bytes (fp8 elems) per pipeline chunk
#define NCHUNK (DIM / BKB)  // 8
#define NSTAGE 2
#define SSTRIDE_B 144       // padded bytes per smem row -> conflict-free ldmatrix
#define A_STAGE_BYTES (BM * SSTRIDE_B)                // 18432
#define B_STAGE_BYTES (BN * SSTRIDE_B)                // 18432
#define STAGE_BYTES   (A_STAGE_BYTES + B_STAGE_BYTES) // 36864
#define SMEM_PIPE     (NSTAGE * STAGE_BYTES)          // 73728
#define RMAX_OFF      SMEM_PIPE                       // 128 floats
#define CMAX_OFF      (SMEM_PIPE + 512)               // 128 floats
#define SMEM_DYN      (SMEM_PIPE + 1024)              // 74752 -> 3 CTAs/SM

#define SCALE 16.0f         // pre-quantization scale; dots carry 256x

// Scratch (no cudaMalloc allowed): fp8 normalized copies + max accumulators.
__device__ unsigned char g_exn8[(size_t)N_ROWS * DIM];
__device__ unsigned char g_eyn8[(size_t)N_ROWS * DIM];
__device__ float g_rowmax[N_ROWS];
__device__ float g_colmax[N_ROWS];

__device__ __forceinline__ void atomicMaxF(float* addr, float val) {
    if (__float_as_int(val) >= 0) {
        atomicMax(reinterpret_cast<int*>(addr), __float_as_int(val));
    } else {
        atomicMin(reinterpret_cast<unsigned int*>(addr), __float_as_uint(val));
    }
}

__device__ __forceinline__ void cp_async16(uint32_t s, const void* g) {
    asm volatile("cp.async.cg.shared.global [%0], [%1], 16;" :: "r"(s), "l"(g));
}
__device__ __forceinline__ void cp_commit() {
    asm volatile("cp.async.commit_group;" ::: "memory");
}
template <int N>
__device__ __forceinline__ void cp_wait() {
    asm volatile("cp.async.wait_group %0;" :: "n"(N) : "memory");
}

// ---------------------------------------------------------------------------
// Kernel 1: fp32 row L2-normalize -> fp8 e4m3; also initializes max arrays.
// ---------------------------------------------------------------------------
__global__ void __launch_bounds__(256) normalize_kernel(const float* __restrict__ ex,
                                                        const float* __restrict__ ey) {
    __shared__ float sh[8];
    int row = blockIdx.x;
    const float* src;
    unsigned char* dst;
    if (row < N_ROWS) {
        src = ex + (size_t)row * DIM;
        dst = g_exn8 + (size_t)row * DIM;
        if (threadIdx.x == 0) g_rowmax[row] = -INFINITY;
    } else {
        src = ey + (size_t)(row - N_ROWS) * DIM;
        dst = g_eyn8 + (size_t)(row - N_ROWS) * DIM;
        if (threadIdx.x == 0) g_colmax[row - N_ROWS] = -INFINITY;
    }
    int tid = threadIdx.x;
    float4 v = reinterpret_cast<const float4*>(src)[tid];
    float ss = v.x * v.x + v.y * v.y + v.z * v.z + v.w * v.w;
    #pragma unroll
    for (int o = 16; o; o >>= 1) ss += __shfl_xor_sync(0xffffffffu, ss, o);
    if ((tid & 31) == 0) sh[tid >> 5] = ss;
    __syncthreads();
    float tot = 0.f;
    #pragma unroll
    for (int w = 0; w < 8; w++) tot += sh[w];
    float inv = rsqrtf(tot) * SCALE;
    uint32_t b0 = __nv_cvt_float_to_fp8(v.x * inv, __NV_SATFINITE, __NV_E4M3);
    uint32_t b1 = __nv_cvt_float_to_fp8(v.y * inv, __NV_SATFINITE, __NV_E4M3);
    uint32_t b2 = __nv_cvt_float_to_fp8(v.z * inv, __NV_SATFINITE, __NV_E4M3);
    uint32_t b3 = __nv_cvt_float_to_fp8(v.w * inv, __NV_SATFINITE, __NV_E4M3);
    reinterpret_cast<uint32_t*>(dst)[tid] = b0 | (b1 << 8) | (b2 << 16) | (b3 << 24);
}

// ---------------------------------------------------------------------------
// Kernel 2: pipelined fp8 mma.sync (f16 acc) GEMM, 128x128 CTA tile, fused
// max-reduce. 8 warps: 4 warp-rows x 2 warp-cols; warp tile 32x64.
// 2-stage pipeline, 3 CTAs/SM (74.75KB smem), ONE barrier per chunk.
// ---------------------------------------------------------------------------
__device__ __forceinline__ void load_chunk(uint32_t sbase, int s, int kc,
                                           int rowBase, int colBase, int tid) {
    uint32_t stA = sbase + s * STAGE_BYTES;
    uint32_t stB = stA + A_STAGE_BYTES;
    const unsigned char* gA = g_exn8 + (size_t)rowBase * DIM + kc * BKB;
    const unsigned char* gB = g_eyn8 + (size_t)colBase * DIM + kc * BKB;
    #pragma unroll
    for (int t = 0; t < 4; t++) {           // A: 128 rows x 128 bytes
        int idx = tid + t * 256;            // 0..1023
        int r = idx >> 3;                   // 0..127
        int c = idx & 7;                    // 16B unit
        cp_async16(stA + r * SSTRIDE_B + c * 16, gA + (size_t)r * DIM + c * 16);
    }
    #pragma unroll
    for (int t = 0; t < 4; t++) {           // B: 128 rows x 128 bytes
        int idx = tid + t * 256;
        int r = idx >> 3;
        int c = idx & 7;
        cp_async16(stB + r * SSTRIDE_B + c * 16, gB + (size_t)r * DIM + c * 16);
    }
}

__global__ void __launch_bounds__(256, 3) gemm_max_kernel() {
    extern __shared__ char dsm[];
    const int tid  = threadIdx.x;
    const int lane = tid & 31;
    const int wid  = tid >> 5;
    const int warpRow = wid & 3;      // 0..3 -> 32-row slab
    const int warpCol = wid >> 2;     // 0..1 -> 64-col slab
    const int rowBase = blockIdx.y * BM;
    const int colBase = blockIdx.x * BN;

    uint32_t sbase = (uint32_t)__cvta_generic_to_shared(dsm);
    float* s_rmax = reinterpret_cast<float*>(dsm + RMAX_OFF);
    float* s_cmax = reinterpret_cast<float*>(dsm + CMAX_OFF);
    if (tid < BM) s_rmax[tid] = -INFINITY;
    if (tid < BN) s_cmax[tid] = -INFINITY;

    // f16 accumulators: [mtile][ntile][rowhalf], each u32 = 2 packed f16 cols
    uint32_t acc[2][8][2];
    #pragma unroll
    for (int i = 0; i < 2; i++)
        #pragma unroll
        for (int j = 0; j < 8; j++) {
            acc[i][j][0] = 0u;
            acc[i][j][1] = 0u;
        }

    load_chunk(sbase, 0, 0, rowBase, colBase, tid); cp_commit();

    for (int ch = 0; ch < NCHUNK; ch++) {
        int s = ch & 1;
        cp_wait<0>();
        __syncthreads();   // (1) stage s data visible to all warps
                           // (2) all reads of stage s^1 from chunk ch-1 done
        if (ch + 1 < NCHUNK) {
            load_chunk(sbase, s ^ 1, ch + 1, rowBase, colBase, tid);
            cp_commit();
        }

        uint32_t stA = sbase + s * STAGE_BYTES;
        uint32_t stB = stA + A_STAGE_BYTES;

        #pragma unroll
        for (int kk = 0; kk < 4; kk++) {     // 4 x k32 steps per 128B chunk
            uint32_t a[2][4];
            uint32_t b[8][2];
            #pragma unroll
            for (int i = 0; i < 2; i++) {
                int r  = warpRow * 32 + i * 16 + ((lane >> 3) & 1) * 8 + (lane & 7);
                int kb = kk * 32 + (lane >> 4) * 16;
                uint32_t addr = stA + r * SSTRIDE_B + kb;
                asm volatile("ldmatrix.sync.aligned.m8n8.x4.shared.b16 {%0,%1,%2,%3}, [%4];"
                             : "=r"(a[i][0]), "=r"(a[i][1]), "=r"(a[i][2]), "=r"(a[i][3])
                             : "r"(addr));
            }
            #pragma unroll
            for (int j = 0; j < 4; j++) {
                int n  = warpCol * 64 + j * 16 + (lane >> 4) * 8 + (lane & 7);
                int kb = kk * 32 + ((lane >> 3) & 1) * 16;
                uint32_t addr = stB + n * SSTRIDE_B + kb;
                asm volatile("ldmatrix.sync.aligned.m8n8.x4.shared.b16 {%0,%1,%2,%3}, [%4];"
                             : "=r"(b[2 * j][0]), "=r"(b[2 * j][1]),
                               "=r"(b[2 * j + 1][0]), "=r"(b[2 * j + 1][1])
                             : "r"(addr));
            }
            #pragma unroll
            for (int i = 0; i < 2; i++)
                #pragma unroll
                for (int j = 0; j < 8; j++)
                    asm volatile(
                        "mma.sync.aligned.m16n8k32.row.col.f16.e4m3.e4m3.f16 "
                        "{%0,%1}, {%2,%3,%4,%5}, {%6,%7}, {%0,%1};"
                        : "+r"(acc[i][j][0]), "+r"(acc[i][j][1])
                        : "r"(a[i][0]), "r"(a[i][1]), "r"(a[i][2]), "r"(a[i][3]),
                          "r"(b[j][0]), "r"(b[j][1]));
        }
    }
    __syncthreads();   // protect s_rmax/s_cmax init + last stage reads

    // ---- Row maxes: reg h covers row groupID+8h, packed pair = 2 adjacent cols.
    #pragma unroll
    for (int i = 0; i < 2; i++) {
        #pragma unroll
        for (int h = 0; h < 2; h++) {
            __half2 hm = *reinterpret_cast<__half2*>(&acc[i][0][h]);
            #pragma unroll
            for (int j = 1; j < 8; j++)
                hm = __hmax2(hm, *reinterpret_cast<__half2*>(&acc[i][j][h]));
            float m = fmaxf(__low2float(hm), __high2float(hm));
            m = fmaxf(m, __shfl_xor_sync(0xffffffffu, m, 1));
            m = fmaxf(m, __shfl_xor_sync(0xffffffffu, m, 2));
            if ((lane & 3) == 0)
                atomicMaxF(&s_rmax[warpRow * 32 + i * 16 + h * 8 + (lane >> 2)], m);
        }
    }
    // ---- Col maxes: packed lanes are 2 adjacent cols -> reduce as half2.
    #pragma unroll
    for (int j = 0; j < 8; j++) {
        __half2 mm = __hmax2(
            __hmax2(*reinterpret_cast<__half2*>(&acc[0][j][0]),
                    *reinterpret_cast<__half2*>(&acc[0][j][1])),
            __hmax2(*reinterpret_cast<__half2*>(&acc[1][j][0]),
                    *reinterpret_cast<__half2*>(&acc[1][j][1])));
        #pragma unroll
        for (int o = 4; o <= 16; o <<= 1) {
            uint32_t u = __shfl_xor_sync(0xffffffffu,
                                         *reinterpret_cast<uint32_t*>(&mm), o);
            mm = __hmax2(mm, *reinterpret_cast<__half2*>(&u));
        }
        if (lane < 4) {
            int cbase = warpCol * 64 + j * 8 + (lane & 3) * 2;
            atomicMaxF(&s_cmax[cbase],     __low2float(mm));
            atomicMaxF(&s_cmax[cbase + 1], __high2float(mm));
        }
    }
    __syncthreads();
    if (tid < BM) atomicMaxF(&g_rowmax[rowBase + tid], s_rmax[tid]);
    if (tid < BN) atomicMaxF(&g_colmax[colBase + tid], s_cmax[tid]);
}

// ---------------------------------------------------------------------------
// Kernel 3: sum max vectors (undo 256x scale), entropy transform, out[2].
// ---------------------------------------------------------------------------
__global__ void __launch_bounds__(1024) finalize_kernel(float* __restrict__ out) {
    __shared__ float sh[64];
    int tid = threadIdx.x;
    float sr = 0.f, sc = 0.f;
    for (int i = tid; i < N_ROWS; i += 1024) {
        sr += g_rowmax[i];
        sc += g_colmax[i];
    }
    #pragma unroll
    for (int o = 16; o; o >>= 1) {
        sr += __shfl_xor_sync(0xffffffffu, sr, o);
        sc += __shfl_xor_sync(0xffffffffu, sc, o);
    }
    if ((tid & 31) == 0) {
        sh[tid >> 5]        = sr;
        sh[32 + (tid >> 5)] = sc;
    }
    __syncthreads();
    if (tid == 0) {
        float SR = 0.f, SC = 0.f;
        #pragma unroll
        for (int w = 0; w < 32; w++) { SR += sh[w]; SC += sh[32 + w]; }
        const float invs2 = 1.0f / (SCALE * SCALE);
        const double sigma = 0.3;
        float hc = (float)(0.5 * log(6.283185307179586 * sigma * sigma) + 0.5);
        out[0] = hc * ((float)N_ROWS - SR * invs2) / 0.3f;
        out[1] = hc * ((float)N_ROWS - SC * invs2) / 0.3f;
    }
}

// ---------------------------------------------------------------------------
extern "C" void kernel_launch(void* const* d_in, const int* in_sizes, int n_in,
                              void* d_out, int out_size) {
    const float* ex = (const float*)d_in[0];
    const float* ey = (const float*)d_in[1];
    float* out = (float*)d_out;

    cudaFuncSetAttribute(gemm_max_kernel,
                         cudaFuncAttributeMaxDynamicSharedMemorySize, SMEM_DYN);

    normalize_kernel<<<2 * N_ROWS, 256>>>(ex, ey);
    dim3 grid(N_ROWS / BN, N_ROWS / BM);
    gemm_max_kernel<<<grid, 256, SMEM_DYN>>>();
    finalize_kernel<<<1, 1024>>>(out);
}

// round 17
// speedup vs baseline: 2.7463x; 1.0296x over previous
#include <cuda_runtime.h>
#include <cuda_bf16.h>
#include <cuda_fp16.h>
#include <cuda_fp8.h>
#include <math.h>
#include <stdint.h>

#define N_ROWS 8192
#define DIM    1024
#define BM     128          // CTA rows (ex)
#define BN     128          // CTA cols (ey)
#define BKB    128          // k bytes (fp8 elems) per pipeline chunk
#define NCHUNK (DIM / BKB)  // 8
#define NSTAGE 2
#define SSTRIDE_B 144       // padded bytes per smem row -> conflict-free ldmatrix
#define A_STAGE_BYTES (BM * SSTRIDE_B)                // 18432
#define B_STAGE_BYTES (BN * SSTRIDE_B)                // 18432
#define STAGE_BYTES   (A_STAGE_BYTES + B_STAGE_BYTES) // 36864
#define SMEM_PIPE     (NSTAGE * STAGE_BYTES)          // 73728
#define RMAX_OFF      SMEM_PIPE                       // 128 floats
#define CMAX_OFF      (SMEM_PIPE + 512)               // 128 floats
#define SMEM_DYN      (SMEM_PIPE + 1024)              // 74752 -> 3 CTAs/SM

#define SCALE 16.0f         // pre-quantization scale; dots carry 256x

// Scratch (no cudaMalloc allowed): fp8 normalized copies + max accumulators.
__device__ unsigned char g_exn8[(size_t)N_ROWS * DIM];
__device__ unsigned char g_eyn8[(size_t)N_ROWS * DIM];
__device__ float g_rowmax[N_ROWS];
__device__ float g_colmax[N_ROWS];

__device__ __forceinline__ void atomicMaxF(float* addr, float val) {
    if (__float_as_int(val) >= 0) {
        atomicMax(reinterpret_cast<int*>(addr), __float_as_int(val));
    } else {
        atomicMin(reinterpret_cast<unsigned int*>(addr), __float_as_uint(val));
    }
}

__device__ __forceinline__ void cp_async16(uint32_t s, const void* g) {
    asm volatile("cp.async.cg.shared.global [%0], [%1], 16;" :: "r"(s), "l"(g));
}
__device__ __forceinline__ void cp_commit() {
    asm volatile("cp.async.commit_group;" ::: "memory");
}
template <int N>
__device__ __forceinline__ void cp_wait() {
    asm volatile("cp.async.wait_group %0;" :: "n"(N) : "memory");
}

// ---------------------------------------------------------------------------
// Kernel 1: fp32 row L2-normalize -> fp8 e4m3; also initializes max arrays.
// 4 rows per block; 64 threads per row; 4 x float4 per thread (MLP=4).
// ---------------------------------------------------------------------------
__global__ void __launch_bounds__(256) normalize_kernel(const float* __restrict__ ex,
                                                        const float* __restrict__ ey) {
    __shared__ float sh[8];
    const int tid = threadIdx.x;
    const int g   = tid >> 6;                 // row group 0..3 within block
    const int sub = tid & 63;                 // thread within row
    const int row = blockIdx.x * 4 + g;       // 0..16383

    const float* src;
    unsigned char* dst;
    if (row < N_ROWS) {
        src = ex + (size_t)row * DIM;
        dst = g_exn8 + (size_t)row * DIM;
        if (sub == 0) g_rowmax[row] = -INFINITY;
    } else {
        src = ey + (size_t)(row - N_ROWS) * DIM;
        dst = g_eyn8 + (size_t)(row - N_ROWS) * DIM;
        if (sub == 0) g_colmax[row - N_ROWS] = -INFINITY;
    }

    const float4* src4 = reinterpret_cast<const float4*>(src);
    float4 v[4];
    #pragma unroll
    for (int q = 0; q < 4; q++) v[q] = src4[sub + 64 * q];

    float ss = 0.f;
    #pragma unroll
    for (int q = 0; q < 4; q++)
        ss += v[q].x * v[q].x + v[q].y * v[q].y + v[q].z * v[q].z + v[q].w * v[q].w;
    #pragma unroll
    for (int o = 16; o; o >>= 1) ss += __shfl_xor_sync(0xffffffffu, ss, o);
    if ((tid & 31) == 0) sh[tid >> 5] = ss;   // 8 warps -> sh[0..7]; row g uses 2g,2g+1
    __syncthreads();
    float inv = rsqrtf(sh[2 * g] + sh[2 * g + 1]) * SCALE;

    uint32_t* dst32 = reinterpret_cast<uint32_t*>(dst);
    #pragma unroll
    for (int q = 0; q < 4; q++) {
        uint32_t b0 = __nv_cvt_float_to_fp8(v[q].x * inv, __NV_SATFINITE, __NV_E4M3);
        uint32_t b1 = __nv_cvt_float_to_fp8(v[q].y * inv, __NV_SATFINITE, __NV_E4M3);
        uint32_t b2 = __nv_cvt_float_to_fp8(v[q].z * inv, __NV_SATFINITE, __NV_E4M3);
        uint32_t b3 = __nv_cvt_float_to_fp8(v[q].w * inv, __NV_SATFINITE, __NV_E4M3);
        dst32[sub + 64 * q] = b0 | (b1 << 8) | (b2 << 16) | (b3 << 24);
    }
}

// ---------------------------------------------------------------------------
// Kernel 2: pipelined fp8 mma.sync (f16 acc) GEMM, 128x128 CTA tile, fused
// max-reduce. 8 warps: 4 warp-rows x 2 warp-cols; warp tile 32x64.
// 2-stage pipeline, 3 CTAs/SM (74.75KB smem), ONE barrier per chunk.
// (UNCHANGED from R10 — proven 343.9us config at the compat-pipe ceiling.)
// ---------------------------------------------------------------------------
__device__ __forceinline__ void load_chunk(uint32_t sbase, int s, int kc,
                                           int rowBase, int colBase, int tid) {
    uint32_t stA = sbase + s * STAGE_BYTES;
    uint32_t stB = stA + A_STAGE_BYTES;
    const unsigned char* gA = g_exn8 + (size_t)rowBase * DIM + kc * BKB;
    const unsigned char* gB = g_eyn8 + (size_t)colBase * DIM + kc * BKB;
    #pragma unroll
    for (int t = 0; t < 4; t++) {           // A: 128 rows x 128 bytes
        int idx = tid + t * 256;            // 0..1023
        int r = idx >> 3;                   // 0..127
        int c = idx & 7;                    // 16B unit
        cp_async16(stA + r * SSTRIDE_B + c * 16, gA + (size_t)r * DIM + c * 16);
    }
    #pragma unroll
    for (int t = 0; t < 4; t++) {           // B: 128 rows x 128 bytes
        int idx = tid + t * 256;
        int r = idx >> 3;
        int c = idx & 7;
        cp_async16(stB + r * SSTRIDE_B + c * 16, gB + (size_t)r * DIM + c * 16);
    }
}

__global__ void __launch_bounds__(256, 3) gemm_max_kernel() {
    extern __shared__ char dsm[];
    const int tid  = threadIdx.x;
    const int lane = tid & 31;
    const int wid  = tid >> 5;
    const int warpRow = wid & 3;      // 0..3 -> 32-row slab
    const int warpCol = wid >> 2;     // 0..1 -> 64-col slab
    const int rowBase = blockIdx.y * BM;
    const int colBase = blockIdx.x * BN;

    uint32_t sbase = (uint32_t)__cvta_generic_to_shared(dsm);
    float* s_rmax = reinterpret_cast<float*>(dsm + RMAX_OFF);
    float* s_cmax = reinterpret_cast<float*>(dsm + CMAX_OFF);
    if (tid < BM) s_rmax[tid] = -INFINITY;
    if (tid < BN) s_cmax[tid] = -INFINITY;

    // f16 accumulators: [mtile][ntile][rowhalf], each u32 = 2 packed f16 cols
    uint32_t acc[2][8][2];
    #pragma unroll
    for (int i = 0; i < 2; i++)
        #pragma unroll
        for (int j = 0; j < 8; j++) {
            acc[i][j][0] = 0u;
            acc[i][j][1] = 0u;
        }

    load_chunk(sbase, 0, 0, rowBase, colBase, tid); cp_commit();

    for (int ch = 0; ch < NCHUNK; ch++) {
        int s = ch & 1;
        cp_wait<0>();
        __syncthreads();   // (1) stage s data visible to all warps
                           // (2) all reads of stage s^1 from chunk ch-1 done
        if (ch + 1 < NCHUNK) {
            load_chunk(sbase, s ^ 1, ch + 1, rowBase, colBase, tid);
            cp_commit();
        }

        uint32_t stA = sbase + s * STAGE_BYTES;
        uint32_t stB = stA + A_STAGE_BYTES;

        #pragma unroll
        for (int kk = 0; kk < 4; kk++) {     // 4 x k32 steps per 128B chunk
            uint32_t a[2][4];
            uint32_t b[8][2];
            #pragma unroll
            for (int i = 0; i < 2; i++) {
                int r  = warpRow * 32 + i * 16 + ((lane >> 3) & 1) * 8 + (lane & 7);
                int kb = kk * 32 + (lane >> 4) * 16;
                uint32_t addr = stA + r * SSTRIDE_B + kb;
                asm volatile("ldmatrix.sync.aligned.m8n8.x4.shared.b16 {%0,%1,%2,%3}, [%4];"
                             : "=r"(a[i][0]), "=r"(a[i][1]), "=r"(a[i][2]), "=r"(a[i][3])
                             : "r"(addr));
            }
            #pragma unroll
            for (int j = 0; j < 4; j++) {
                int n  = warpCol * 64 + j * 16 + (lane >> 4) * 8 + (lane & 7);
                int kb = kk * 32 + ((lane >> 3) & 1) * 16;
                uint32_t addr = stB + n * SSTRIDE_B + kb;
                asm volatile("ldmatrix.sync.aligned.m8n8.x4.shared.b16 {%0,%1,%2,%3}, [%4];"
                             : "=r"(b[2 * j][0]), "=r"(b[2 * j][1]),
                               "=r"(b[2 * j + 1][0]), "=r"(b[2 * j + 1][1])
                             : "r"(addr));
            }
            #pragma unroll
            for (int i = 0; i < 2; i++)
                #pragma unroll
                for (int j = 0; j < 8; j++)
                    asm volatile(
                        "mma.sync.aligned.m16n8k32.row.col.f16.e4m3.e4m3.f16 "
                        "{%0,%1}, {%2,%3,%4,%5}, {%6,%7}, {%0,%1};"
                        : "+r"(acc[i][j][0]), "+r"(acc[i][j][1])
                        : "r"(a[i][0]), "r"(a[i][1]), "r"(a[i][2]), "r"(a[i][3]),
                          "r"(b[j][0]), "r"(b[j][1]));
        }
    }
    __syncthreads();   // protect s_rmax/s_cmax init + last stage reads

    // ---- Row maxes: reg h covers row groupID+8h, packed pair = 2 adjacent cols.
    #pragma unroll
    for (int i = 0; i < 2; i++) {
        #pragma unroll
        for (int h = 0; h < 2; h++) {
            __half2 hm = *reinterpret_cast<__half2*>(&acc[i][0][h]);
            #pragma unroll
            for (int j = 1; j < 8; j++)
                hm = __hmax2(hm, *reinterpret_cast<__half2*>(&acc[i][j][h]));
            float m = fmaxf(__low2float(hm), __high2float(hm));
            m = fmaxf(m, __shfl_xor_sync(0xffffffffu, m, 1));
            m = fmaxf(m, __shfl_xor_sync(0xffffffffu, m, 2));
            if ((lane & 3) == 0)
                atomicMaxF(&s_rmax[warpRow * 32 + i * 16 + h * 8 + (lane >> 2)], m);
        }
    }
    // ---- Col maxes: packed lanes are 2 adjacent cols -> reduce as half2.
    #pragma unroll
    for (int j = 0; j < 8; j++) {
        __half2 mm = __hmax2(
            __hmax2(*reinterpret_cast<__half2*>(&acc[0][j][0]),
                    *reinterpret_cast<__half2*>(&acc[0][j][1])),
            __hmax2(*reinterpret_cast<__half2*>(&acc[1][j][0]),
                    *reinterpret_cast<__half2*>(&acc[1][j][1])));
        #pragma unroll
        for (int o = 4; o <= 16; o <<= 1) {
            uint32_t u = __shfl_xor_sync(0xffffffffu,
                                         *reinterpret_cast<uint32_t*>(&mm), o);
            mm = __hmax2(mm, *reinterpret_cast<__half2*>(&u));
        }
        if (lane < 4) {
            int cbase = warpCol * 64 + j * 8 + (lane & 3) * 2;
            atomicMaxF(&s_cmax[cbase],     __low2float(mm));
            atomicMaxF(&s_cmax[cbase + 1], __high2float(mm));
        }
    }
    __syncthreads();
    if (tid < BM) atomicMaxF(&g_rowmax[rowBase + tid], s_rmax[tid]);
    if (tid < BN) atomicMaxF(&g_colmax[colBase + tid], s_cmax[tid]);
}

// ---------------------------------------------------------------------------
// Kernel 3: sum max vectors (undo 256x scale), entropy transform, out[2].
// 1024 threads; 8 fully unrolled independent loads per array (MLP 16).
// ---------------------------------------------------------------------------
__global__ void __launch_bounds__(1024) finalize_kernel(float* __restrict__ out) {
    __shared__ float sh[64];
    int tid = threadIdx.x;
    float r[8], c[8];
    #pragma unroll
    for (int q = 0; q < 8; q++) {
        r[q] = g_rowmax[tid + q * 1024];
        c[q] = g_colmax[tid + q * 1024];
    }
    float sr = 0.f, sc = 0.f;
    #pragma unroll
    for (int q = 0; q < 8; q++) { sr += r[q]; sc += c[q]; }
    #pragma unroll
    for (int o = 16; o; o >>= 1) {
        sr += __shfl_xor_sync(0xffffffffu, sr, o);
        sc += __shfl_xor_sync(0xffffffffu, sc, o);
    }
    if ((tid & 31) == 0) {
        sh[tid >> 5]        = sr;
        sh[32 + (tid >> 5)] = sc;
    }
    __syncthreads();
    if (tid == 0) {
        float SR = 0.f, SC = 0.f;
        #pragma unroll
        for (int w = 0; w < 32; w++) { SR += sh[w]; SC += sh[32 + w]; }
        const float invs2 = 1.0f / (SCALE * SCALE);
        const double sigma = 0.3;
        float hc = (float)(0.5 * log(6.283185307179586 * sigma * sigma) + 0.5);
        out[0] = hc * ((float)N_ROWS - SR * invs2) / 0.3f;
        out[1] = hc * ((float)N_ROWS - SC * invs2) / 0.3f;
    }
}

// ---------------------------------------------------------------------------
extern "C" void kernel_launch(void* const* d_in, const int* in_sizes, int n_in,
                              void* d_out, int out_size) {
    const float* ex = (const float*)d_in[0];
    const float* ey = (const float*)d_in[1];
    float* out = (float*)d_out;

    cudaFuncSetAttribute(gemm_max_kernel,
                         cudaFuncAttributeMaxDynamicSharedMemorySize, SMEM_DYN);

    normalize_kernel<<<(2 * N_ROWS) / 4, 256>>>(ex, ey);
    dim3 grid(N_ROWS / BN, N_ROWS / BM);
    gemm_max_kernel<<<grid, 256, SMEM_DYN>>>();
    finalize_kernel<<<1, 1024>>>(out);
}